// round 13
// baseline (speedup 1.0000x reference)
#include <cuda_runtime.h>
#include <cuda_fp16.h>
#include <math.h>
#include <stdint.h>

// Problem constants
#define NI 2048
#define KSEN 16
#define H 768
#define H2 1536
#define RR (NI*KSEN)   // 32768

// ---------------- device scratch (static; no allocations) ----------------
__device__ float g_predcat[NI*H2];   // concat(pred_dec, pred_gls) [N,2H]
__device__ float g_score[NI];
__device__ int   g_sel;
__device__ int   g_flag;
__device__ float g_bias_attn[H];     // sel_mg@W1 + W1_b + W2_b
__device__ float g_bias_v[H];        // sel_mg@V1 + V1_b + V2_b
__device__ float g_M[H*2];           // U_w @ cls_w
__device__ float g_c2[2];            // U_b @ cls_w
__device__ float g_logit_part[(size_t)RR*12];
__device__ float g_rv_part[(size_t)RR*24];  // [r][12][2]

// fp16 operands
__device__ __half g_Ah[(size_t)RR*H2];       // big-GEMM A (~100.7 MB)
__device__ __half g_Bh[(size_t)H2*H2];       // big-GEMM B [n][k]; n<768: W2 col n, else V2 col n-768
__device__ __half g_Fh[(size_t)NI*H2];       // feat hi  [n][k]
__device__ __half g_Fl[(size_t)NI*H2];       // feat lo
__device__ __half g_S1h[(size_t)H*H2];       // s1_w^T hi [o][i]
__device__ __half g_S1l[(size_t)H*H2];       // s1_w^T lo

// ---------------- helpers ----------------
__device__ __forceinline__ float wsum(float v){
    #pragma unroll
    for (int o=16;o;o>>=1) v += __shfl_xor_sync(0xffffffffu, v, o);
    return v;
}
__device__ __forceinline__ uint32_t smem_u32(const void* p){
    uint32_t a;
    asm("{ .reg .u64 t; cvta.to.shared.u64 t, %1; cvt.u32.u64 %0, t; }" : "=r"(a) : "l"(p));
    return a;
}
__device__ __forceinline__ void ldm4(uint32_t* r, uint32_t addr){
    asm volatile("ldmatrix.sync.aligned.m8n8.x4.shared.b16 {%0,%1,%2,%3}, [%4];"
        : "=r"(r[0]),"=r"(r[1]),"=r"(r[2]),"=r"(r[3]) : "r"(addr));
}
__device__ __forceinline__ void mma_f16(float* c, const uint32_t* a, uint32_t b0, uint32_t b1){
    asm volatile("mma.sync.aligned.m16n8k16.row.col.f32.f16.f16.f32 "
        "{%0,%1,%2,%3}, {%4,%5,%6,%7}, {%8,%9}, {%0,%1,%2,%3};"
        : "+f"(c[0]),"+f"(c[1]),"+f"(c[2]),"+f"(c[3])
        : "r"(a[0]),"r"(a[1]),"r"(a[2]),"r"(a[3]), "r"(b0),"r"(b1));
}
__device__ __forceinline__ void cpa16(uint32_t s, const void* g){
    asm volatile("cp.async.cg.shared.global [%0], [%1], 16;" :: "r"(s), "l"(g));
}
__device__ __forceinline__ void cpa_commit(){ asm volatile("cp.async.commit_group;" ::: "memory"); }
__device__ __forceinline__ void cpa_wait1(){ asm volatile("cp.async.wait_group 1;" ::: "memory"); }

// ---------------- L1: pool(+conversions) / W2|V2 transpose / s1_w transpose+split ----------------
__global__ void k_pool_conv(const float* __restrict__ dec, const float* __restrict__ gls,
                            const int* __restrict__ pred,
                            const float* __restrict__ W2, const float* __restrict__ V2,
                            const float* __restrict__ s1w){
    int bid = blockIdx.x;
    if (bid == 0 && threadIdx.x == 0) g_flag = 0;
    if (bid < NI){
        int n = bid;
        int p = pred[n];
        if (threadIdx.x == 0) g_score[n] = 0.f;
        const float* db = dec + (size_t)n*KSEN*H;
        const float* gb = gls + (size_t)n*KSEN*H;
        for (int dp = threadIdx.x; dp < H/2; dp += blockDim.x){
            int d = dp*2;
            float sd0=0.f, sd1=0.f, sg0=0.f, sg1=0.f;
            #pragma unroll
            for (int k=0;k<KSEN;k++){
                float2 vd = *(const float2*)(db + k*H + d);
                float2 vg = *(const float2*)(gb + k*H + d);
                sd0 += vd.x; sd1 += vd.y; sg0 += vg.x; sg1 += vg.y;
                size_t r = (size_t)(n*KSEN + k);
                *(__half2*)(g_Ah + r*H2 + d)     = __floats2half2_rn(vd.x, vd.y);
                *(__half2*)(g_Ah + r*H2 + H + d) = __floats2half2_rn(vg.x, vg.y);
            }
            float2 pd = *(const float2*)(db + p*H + d);
            float2 pg = *(const float2*)(gb + p*H + d);
            float f0 = pd.x - sd0*(1.0f/16.0f), f1 = pd.y - sd1*(1.0f/16.0f);
            float h0 = pg.x - sg0*(1.0f/16.0f), h1 = pg.y - sg1*(1.0f/16.0f);
            __half fh0 = __float2half_rn(f0), fh1 = __float2half_rn(f1);
            __half hh0 = __float2half_rn(h0), hh1 = __float2half_rn(h1);
            size_t fb = (size_t)n*H2;
            *(__half2*)(g_Fh + fb + d)     = __half2(fh0, fh1);
            *(__half2*)(g_Fh + fb + H + d) = __half2(hh0, hh1);
            *(__half2*)(g_Fl + fb + d)     = __floats2half2_rn(f0-__half2float(fh0), f1-__half2float(fh1));
            *(__half2*)(g_Fl + fb + H + d) = __floats2half2_rn(h0-__half2float(hh0), h1-__half2float(hh1));
            *(float2*)(g_predcat + fb + d)     = pd;
            *(float2*)(g_predcat + fb + H + d) = pg;
        }
    } else if (bid < NI + 2304){
        __shared__ float tile[32][33];
        int cbid = bid - NI;
        int nb = cbid / 48;
        int kb = cbid % 48;
        int tx = threadIdx.x & 31, ty = threadIdx.x >> 5;
        const float* src = (nb < 24) ? W2 : V2;
        int col0 = (nb % 24) * 32;
        #pragma unroll
        for (int j=0;j<4;j++){
            int kk = ty + j*8;
            tile[tx][kk] = src[(size_t)(kb*32 + kk)*H + col0 + tx];
        }
        __syncthreads();
        int n0 = nb*32;
        #pragma unroll
        for (int j=0;j<4;j++){
            int c = ty + j*8;
            size_t di = (size_t)(n0 + c)*H2 + kb*32 + tx;
            g_Bh[di] = __float2half_rn(tile[c][tx]);
        }
    } else {
        __shared__ float tile[32][33];
        int cbid = bid - NI - 2304;
        int ob = cbid / 48;
        int kb = cbid % 48;
        int tx = threadIdx.x & 31, ty = threadIdx.x >> 5;
        int o0 = ob*32;
        #pragma unroll
        for (int j=0;j<4;j++){
            int kk = ty + j*8;
            tile[tx][kk] = s1w[(size_t)(kb*32 + kk)*H + o0 + tx];
        }
        __syncthreads();
        #pragma unroll
        for (int j=0;j<4;j++){
            int c = ty + j*8;
            float v = tile[c][tx];
            __half hi = __float2half_rn(v);
            size_t di = (size_t)(o0 + c)*H2 + kb*32 + tx;
            g_S1h[di] = hi;
            g_S1l[di] = __float2half_rn(v - __half2float(hi));
        }
    }
}

// ---------------- L2: tensor-core gemm1: score partials via 3-product fp16 split ----------------
#define G1_REGION 18432
#define G1_STAGE  73728
#define G1_SMEM   (3*G1_STAGE)
#define G1_ITERS  24

__device__ __forceinline__ void g1_load_stage(uint32_t sb, int stage, int by, int cb, int gk, int tid){
    uint32_t s0 = sb + stage*G1_STAGE;
    #pragma unroll
    for (int j=0;j<16;j++){
        int idx = j*256 + tid;
        int region = idx >> 10;
        int cl = idx & 1023;
        int r  = cl >> 3;
        int kc = cl & 7;
        const __half* g;
        size_t grow;
        if (region == 0){ g = g_Fh;  grow = (size_t)(by*128 + r); }
        else if (region == 1){ g = g_Fl;  grow = (size_t)(by*128 + r); }
        else if (region == 2){ g = g_S1h; grow = (size_t)(cb*128 + r); }
        else { g = g_S1l; grow = (size_t)(cb*128 + r); }
        cpa16(s0 + region*G1_REGION + r*144 + kc*16, g + grow*H2 + gk + kc*8);
    }
}

__global__ void __launch_bounds__(256,1) k_gemm1t(const float* __restrict__ s1b,
                                                  const float* __restrict__ s2w){
    extern __shared__ char smem[];
    uint32_t sb = smem_u32(smem);
    int tid = threadIdx.x;
    int cb = blockIdx.x, by = blockIdx.y;
    int warp = tid >> 5, lane = tid & 31;
    int wm = warp & 3, wn = warp >> 2;

    float acc[2][8][4];
    #pragma unroll
    for (int mt=0;mt<2;mt++)
        #pragma unroll
        for (int nt=0;nt<8;nt++)
            #pragma unroll
            for (int d=0;d<4;d++) acc[mt][nt][d] = 0.f;

    g1_load_stage(sb, 0, by, cb, 0,  tid); cpa_commit();
    g1_load_stage(sb, 1, by, cb, 64, tid); cpa_commit();

    int m8 = lane >> 3, r8 = lane & 7;

    for (int it = 0; it < G1_ITERS; it++){
        cpa_wait1();
        __syncthreads();
        if (it + 2 < G1_ITERS) g1_load_stage(sb, (it+2)%3, by, cb, (it+2)*64, tid);
        cpa_commit();

        uint32_t st = sb + (it%3)*G1_STAGE;
        #pragma unroll
        for (int kh=0; kh<4; kh++){
            int k0 = kh*16;
            uint32_t ah[2][4], al[2][4], bb[4][4];
            #pragma unroll
            for (int mt=0;mt<2;mt++){
                int rowA = wm*32 + mt*16 + (m8&1)*8 + r8;
                int kA   = k0 + (m8>>1)*8;
                uint32_t aoff = rowA*144 + kA*2;
                ldm4(ah[mt], st + 0*G1_REGION + aoff);
                ldm4(al[mt], st + 1*G1_REGION + aoff);
            }
            int rowB = wn*64 + (m8>>1)*8 + r8;
            int kB   = k0 + (m8&1)*8;
            uint32_t boff = rowB*144 + kB*2;
            #pragma unroll
            for (int ntp=0;ntp<4;ntp++) ldm4(bb[ntp], st + 2*G1_REGION + boff + ntp*16*144);
            #pragma unroll
            for (int mt=0;mt<2;mt++)
                #pragma unroll
                for (int nt=0;nt<8;nt++)
                    mma_f16(acc[mt][nt], ah[mt], bb[nt>>1][(nt&1)*2], bb[nt>>1][(nt&1)*2+1]);
            #pragma unroll
            for (int mt=0;mt<2;mt++)
                #pragma unroll
                for (int nt=0;nt<8;nt++)
                    mma_f16(acc[mt][nt], al[mt], bb[nt>>1][(nt&1)*2], bb[nt>>1][(nt&1)*2+1]);
            #pragma unroll
            for (int ntp=0;ntp<4;ntp++) ldm4(bb[ntp], st + 3*G1_REGION + boff + ntp*16*144);
            #pragma unroll
            for (int mt=0;mt<2;mt++)
                #pragma unroll
                for (int nt=0;nt<8;nt++)
                    mma_f16(acc[mt][nt], ah[mt], bb[nt>>1][(nt&1)*2], bb[nt>>1][(nt&1)*2+1]);
        }
    }

    int quad = lane >> 2, qt = lane & 3;
    int colb = cb*128;
    #pragma unroll
    for (int mt=0;mt<2;mt++){
        float plo = 0.f, phi = 0.f;
        #pragma unroll
        for (int nt=0;nt<8;nt++){
            int g0 = colb + wn*64 + nt*8 + qt*2;
            float b0 = s1b[g0], b1 = s1b[g0+1];
            float w0 = s2w[g0], w1 = s2w[g0+1];
            float x;
            x = acc[mt][nt][0]+b0; x = x>0.f? x:0.f; plo += x*w0;
            x = acc[mt][nt][1]+b1; x = x>0.f? x:0.f; plo += x*w1;
            x = acc[mt][nt][2]+b0; x = x>0.f? x:0.f; phi += x*w0;
            x = acc[mt][nt][3]+b1; x = x>0.f? x:0.f; phi += x*w1;
        }
        plo += __shfl_xor_sync(0xffffffffu, plo, 1);
        plo += __shfl_xor_sync(0xffffffffu, plo, 2);
        phi += __shfl_xor_sync(0xffffffffu, phi, 1);
        phi += __shfl_xor_sync(0xffffffffu, phi, 2);
        if (qt == 0){
            int rlo = by*128 + wm*32 + mt*16 + quad;
            atomicAdd(&g_score[rlo],   plo);
            atomicAdd(&g_score[rlo+8], phi);
        }
    }
}

// ---------------- L3: softmax (block 0) + sel-dependent biases + M (blocks 1..36) ----------------
__global__ void __launch_bounds__(1024) k_softmax_bias(
    float* __restrict__ probs,
    const float* __restrict__ W1, const float* __restrict__ W1b, const float* __restrict__ W2b,
    const float* __restrict__ V1, const float* __restrict__ V1b, const float* __restrict__ V2b,
    const float* __restrict__ Uw, const float* __restrict__ Ub,
    const float* __restrict__ clsw){
    int b = blockIdx.x, tid = threadIdx.x;
    if (b == 0){
        __shared__ float sv[1024];
        __shared__ int   si[1024];
        float a=g_score[tid], bb=g_score[tid+1024];
        float m; int mi;
        if (a>=bb){ m=a; mi=tid; } else { m=bb; mi=tid+1024; }
        sv[tid]=m; si[tid]=mi;
        __syncthreads();
        for (int s=512;s>0;s>>=1){
            if (tid<s){
                float ov=sv[tid+s]; int oi=si[tid+s];
                if (ov>sv[tid] || (ov==sv[tid] && oi<si[tid])){ sv[tid]=ov; si[tid]=oi; }
            }
            __syncthreads();
        }
        float mx = sv[0]; int sel = si[0];
        if (tid==0) g_sel = sel;
        __syncthreads();
        float e0 = expf(a-mx), e1 = expf(bb-mx);
        sv[tid] = e0+e1;
        __syncthreads();
        for (int s=512;s>0;s>>=1){ if (tid<s) sv[tid]+=sv[tid+s]; __syncthreads(); }
        float inv = 1.0f/sv[0];
        probs[tid]      = e0*inv;
        probs[tid+1024] = e1*inv;
        __threadfence();
        __syncthreads();
        if (tid==0) atomicExch(&g_flag, 1);
        return;
    }
    if (tid == 0){ while (atomicAdd(&g_flag, 0) == 0) __nanosleep(64); }
    __syncthreads();
    __threadfence();
    if (b <= 12){
        __shared__ float red[8][128];
        int g = b - 1;
        int half = (g >= 6);
        int jbase = (half ? g-6 : g) * 128;
        int jj = tid & 127, c = tid >> 7;
        int sel = g_sel;
        const float* m = half ? V1 : W1;
        const float* srow = g_predcat + (size_t)sel*H2;
        int j = jbase + jj;
        float s = 0.f;
        int i0 = c*192;
        #pragma unroll 4
        for (int i=i0; i<i0+192; i++) s += srow[i]*m[(size_t)i*H + j];
        red[c][jj] = s;
        __syncthreads();
        if (c == 0){
            float t = 0.f;
            #pragma unroll
            for (int cc=0; cc<8; cc++) t += red[cc][jj];
            if (half) g_bias_v[j]    = t + V1b[j] + V2b[j];
            else      g_bias_attn[j] = t + W1b[j] + W2b[j];
        }
    } else {
        int w = tid >> 5, lane = tid & 31;
        int j = (b-13)*32 + w;
        const float* ur = Uw + (size_t)j*H;
        float m0=0.f, m1=0.f;
        for (int t=lane; t<H; t+=32){ float u=ur[t]; m0+=u*clsw[2*t]; m1+=u*clsw[2*t+1]; }
        m0 = wsum(m0); m1 = wsum(m1);
        if (lane==0){ g_M[2*j]=m0; g_M[2*j+1]=m1; }
        if (b==13 && w==1){
            float s0=0.f, s1=0.f;
            for (int t=lane; t<H; t+=32){ float u=Ub[t]; s0+=u*clsw[2*t]; s1+=u*clsw[2*t+1]; }
            s0 = wsum(s0); s1 = wsum(s1);
            if (lane==0){ g_c2[0]=s0; g_c2[1]=s1; }
        }
    }
}

// ---------------- L4: mma.sync fp16 GEMM, 64x64 warp tiles (128 thr) + reduce ----------------
// grid (12, 256), CTA 128x128, 128 thr, warps 2(M)x2(N), warp tile 64x64.
// 3-stage K64 cp.async pipeline, occupancy 2, one barrier/iter.
#define KB_REGION 18432
#define KB_STAGE  36864
#define KB_SMEM   (3*KB_STAGE)
#define KB_ITERS  24

__device__ __forceinline__ void kb_load_stage(uint32_t sb, int stage, int by, int cb, int gk, int tid){
    uint32_t s0 = sb + stage*KB_STAGE;
    #pragma unroll
    for (int j=0;j<16;j++){
        int idx = j*128 + tid;        // 0..2047
        int region = idx >> 10;       // 0 A, 1 Bh
        int cl = idx & 1023;
        int r  = cl >> 3;
        int kc = cl & 7;
        const __half* g = region ? g_Bh : g_Ah;
        size_t grow = region ? (size_t)(cb*128 + r) : (size_t)(by*128 + r);
        cpa16(s0 + region*KB_REGION + r*144 + kc*16, g + grow*H2 + gk + kc*8);
    }
}

__global__ void __launch_bounds__(128,2) k_big_mma(const float* __restrict__ Wa){
    extern __shared__ char smem[];
    uint32_t sb = smem_u32(smem);
    int tid = threadIdx.x;
    int cb = blockIdx.x, by = blockIdx.y;
    int warp = tid >> 5, lane = tid & 31;
    int wm = warp & 1, wn = warp >> 1;      // wm 0..1 (64 M-rows), wn 0..1 (64 N-cols)

    float acc[4][8][4];
    #pragma unroll
    for (int mt=0;mt<4;mt++)
        #pragma unroll
        for (int nt=0;nt<8;nt++)
            #pragma unroll
            for (int d=0;d<4;d++) acc[mt][nt][d] = 0.f;

    kb_load_stage(sb, 0, by, cb, 0,  tid); cpa_commit();
    kb_load_stage(sb, 1, by, cb, 64, tid); cpa_commit();

    int m8 = lane >> 3, r8 = lane & 7;

    for (int it = 0; it < KB_ITERS; it++){
        cpa_wait1();
        __syncthreads();
        if (it + 2 < KB_ITERS) kb_load_stage(sb, (it+2)%3, by, cb, (it+2)*64, tid);
        cpa_commit();

        uint32_t st = sb + (it%3)*KB_STAGE;
        #pragma unroll
        for (int kh=0; kh<4; kh++){
            int k0 = kh*16;
            uint32_t ah[4][4], bb[4][4];
            #pragma unroll
            for (int mt=0;mt<4;mt++){
                int rowA = wm*64 + mt*16 + (m8&1)*8 + r8;
                int kA   = k0 + (m8>>1)*8;
                ldm4(ah[mt], st + 0*KB_REGION + rowA*144 + kA*2);
            }
            int rowB = wn*64 + (m8>>1)*8 + r8;
            int kB   = k0 + (m8&1)*8;
            uint32_t boff = rowB*144 + kB*2;
            #pragma unroll
            for (int ntp=0;ntp<4;ntp++) ldm4(bb[ntp], st + 1*KB_REGION + boff + ntp*16*144);
            #pragma unroll
            for (int mt=0;mt<4;mt++)
                #pragma unroll
                for (int nt=0;nt<8;nt++)
                    mma_f16(acc[mt][nt], ah[mt], bb[nt>>1][(nt&1)*2], bb[nt>>1][(nt&1)*2+1]);
        }
    }

    // ---------------- epilogue: reduce over the 128 columns this CTA owns ----------------
    int quad = lane >> 2, qt = lane & 3;
    if (cb < 6){
        int colb = cb*128;
        #pragma unroll
        for (int mt=0;mt<4;mt++){
            float plo = 0.f, phi = 0.f;
            #pragma unroll
            for (int nt=0;nt<8;nt++){
                int g0 = colb + wn*64 + nt*8 + qt*2;
                float ba0 = g_bias_attn[g0],  ba1 = g_bias_attn[g0+1];
                float w0  = Wa[g0],           w1  = Wa[g0+1];
                plo += tanhf(acc[mt][nt][0]+ba0)*w0 + tanhf(acc[mt][nt][1]+ba1)*w1;
                phi += tanhf(acc[mt][nt][2]+ba0)*w0 + tanhf(acc[mt][nt][3]+ba1)*w1;
            }
            plo += __shfl_xor_sync(0xffffffffu, plo, 1);
            plo += __shfl_xor_sync(0xffffffffu, plo, 2);
            phi += __shfl_xor_sync(0xffffffffu, phi, 1);
            phi += __shfl_xor_sync(0xffffffffu, phi, 2);
            if (qt == 0){
                int rlo = by*128 + wm*64 + mt*16 + quad;
                g_logit_part[(size_t)rlo*12 + cb*2 + wn]     = plo;
                g_logit_part[(size_t)(rlo+8)*12 + cb*2 + wn] = phi;
            }
        }
    } else {
        int cbv = cb - 6, colb = cbv*128, slot = cbv*2 + wn;
        #pragma unroll
        for (int mt=0;mt<4;mt++){
            float p0l=0.f, p1l=0.f, p0h=0.f, p1h=0.f;
            #pragma unroll
            for (int nt=0;nt<8;nt++){
                int g0 = colb + wn*64 + nt*8 + qt*2;
                float bv0 = g_bias_v[g0], bv1 = g_bias_v[g0+1];
                float m00 = g_M[2*g0],   m01 = g_M[2*g0+1];
                float m10 = g_M[2*g0+2], m11 = g_M[2*g0+3];
                float x;
                x = acc[mt][nt][0]+bv0; x = x>0.f? x:0.f; p0l += x*m00; p1l += x*m01;
                x = acc[mt][nt][1]+bv1; x = x>0.f? x:0.f; p0l += x*m10; p1l += x*m11;
                x = acc[mt][nt][2]+bv0; x = x>0.f? x:0.f; p0h += x*m00; p1h += x*m01;
                x = acc[mt][nt][3]+bv1; x = x>0.f? x:0.f; p0h += x*m10; p1h += x*m11;
            }
            p0l += __shfl_xor_sync(0xffffffffu, p0l, 1); p0l += __shfl_xor_sync(0xffffffffu, p0l, 2);
            p1l += __shfl_xor_sync(0xffffffffu, p1l, 1); p1l += __shfl_xor_sync(0xffffffffu, p1l, 2);
            p0h += __shfl_xor_sync(0xffffffffu, p0h, 1); p0h += __shfl_xor_sync(0xffffffffu, p0h, 2);
            p1h += __shfl_xor_sync(0xffffffffu, p1h, 1); p1h += __shfl_xor_sync(0xffffffffu, p1h, 2);
            if (qt == 0){
                int rlo = by*128 + wm*64 + mt*16 + quad;
                g_rv_part[(size_t)rlo*24 + slot*2 + 0] = p0l;
                g_rv_part[(size_t)rlo*24 + slot*2 + 1] = p1l;
                g_rv_part[(size_t)(rlo+8)*24 + slot*2 + 0] = p0h;
                g_rv_part[(size_t)(rlo+8)*24 + slot*2 + 1] = p1h;
            }
        }
    }
}

// ---------------- L5: fused per-instance attn softmax + final logits ----------------
__global__ void __launch_bounds__(512) k_attn_final(const float* __restrict__ dec,
                                                    const float* __restrict__ clsw,
                                                    const float* __restrict__ clsb,
                                                    float* __restrict__ out){
    __shared__ float slg[16];
    __shared__ float sat[16];
    int n = blockIdx.x;
    int w = threadIdx.x >> 5, lane = threadIdx.x & 31;
    int r = n*KSEN + w;
    const float* drow = dec + (size_t)r*H;
    float a0=0.f, a1=0.f;
    #pragma unroll 4
    for (int t=lane;t<H;t+=32){ float d=drow[t]; a0 += d*clsw[2*t]; a1 += d*clsw[2*t+1]; }
    a0 = wsum(a0); a1 = wsum(a1);
    float lgp = (lane < 12) ? g_logit_part[(size_t)r*12 + lane] : 0.f;
    float lg = wsum(lgp);
    if (lane == 0) slg[w] = lg;
    __syncthreads();
    if (w == 0){
        float v = (lane < 16) ? slg[lane] : -INFINITY;
        float m = v;
        #pragma unroll
        for (int o=16;o;o>>=1) m = fmaxf(m, __shfl_xor_sync(0xffffffffu, m, o));
        float e = (lane < 16) ? expf(v - m) : 0.f;
        float s = wsum(e);
        if (lane < 16) sat[lane] = e/s;
    }
    float rv0p = (lane < 12) ? g_rv_part[(size_t)r*24 + lane*2]     : 0.f;
    float rv1p = (lane < 12) ? g_rv_part[(size_t)r*24 + lane*2 + 1] : 0.f;
    float rv0 = wsum(rv0p), rv1 = wsum(rv1p);
    __syncthreads();
    if (lane == 0){
        float o0 = a0 + clsb[0], o1 = a1 + clsb[1];
        if (n != g_sel){
            float at = sat[w];
            o0 += at*(rv0 + g_c2[0]);
            o1 += at*(rv1 + g_c2[1]);
        }
        out[2*r]   = o0;
        out[2*r+1] = o1;
    }
}

// ---------------- launcher ----------------
extern "C" void kernel_launch(void* const* d_in, const int* in_sizes, int n_in,
                              void* d_out, int out_size){
    (void)n_in; (void)out_size;
    const float *dec,*gls,*s1w,*s1b,*s2w,*s2b,*W1w,*W1b,*W2w,*W2b,*Waw,*Wab,*V1w,*V1b,*V2w,*V2b,*Uw,*Ub,*clsw,*clsb;
    const int* pred;
    if (in_sizes[2] == NI){
        dec=(const float*)d_in[0]; gls=(const float*)d_in[1]; pred=(const int*)d_in[2];
        s1w=(const float*)d_in[3];  s1b=(const float*)d_in[4];
        s2w=(const float*)d_in[5];  s2b=(const float*)d_in[6];
        W1w=(const float*)d_in[7];  W1b=(const float*)d_in[8];
        W2w=(const float*)d_in[9];  W2b=(const float*)d_in[10];
        Waw=(const float*)d_in[11]; Wab=(const float*)d_in[12];
        V1w=(const float*)d_in[13]; V1b=(const float*)d_in[14];
        V2w=(const float*)d_in[15]; V2b=(const float*)d_in[16];
        Uw =(const float*)d_in[17]; Ub =(const float*)d_in[18];
        clsw=(const float*)d_in[19]; clsb=(const float*)d_in[20];
    } else {
        dec=(const float*)d_in[0]; gls=(const float*)d_in[1];
        s1w=(const float*)d_in[2];  s1b=(const float*)d_in[3];
        s2w=(const float*)d_in[4];  s2b=(const float*)d_in[5];
        W1w=(const float*)d_in[6];  W1b=(const float*)d_in[7];
        W2w=(const float*)d_in[8];  W2b=(const float*)d_in[9];
        Waw=(const float*)d_in[10]; Wab=(const float*)d_in[11];
        V1w=(const float*)d_in[12]; V1b=(const float*)d_in[13];
        V2w=(const float*)d_in[14]; V2b=(const float*)d_in[15];
        Uw =(const float*)d_in[16]; Ub =(const float*)d_in[17];
        clsw=(const float*)d_in[18]; clsb=(const float*)d_in[19];
        pred=(const int*)d_in[20];
    }
    (void)s2b; (void)Wab;
    float* out = (float*)d_out;

    cudaFuncSetAttribute(k_gemm1t,  cudaFuncAttributeMaxDynamicSharedMemorySize, G1_SMEM);
    cudaFuncSetAttribute(k_big_mma, cudaFuncAttributeMaxDynamicSharedMemorySize, KB_SMEM);

    k_pool_conv   <<<NI + 2304 + 1152, 256>>>(dec, gls, pred, W2w, V2w, s1w);
    k_gemm1t      <<<dim3(6,16), 256, G1_SMEM>>>(s1b, s2w);
    k_softmax_bias<<<37, 1024>>>(out + 2*RR, W1w, W1b, W2b, V1w, V1b, V2b, Uw, Ub, clsw);
    k_big_mma     <<<dim3(12, 256), 128, KB_SMEM>>>(Waw);   // launch #4 -> profiled
    k_attn_final  <<<NI, 512>>>(dec, clsw, clsb, out);
}

// round 14
// speedup vs baseline: 1.1381x; 1.1381x over previous
#include <cuda_runtime.h>
#include <cuda_fp16.h>
#include <math.h>
#include <stdint.h>

// Problem constants
#define NI 2048
#define KSEN 16
#define H 768
#define H2 1536
#define RR (NI*KSEN)   // 32768

// ---------------- device scratch (static; no allocations) ----------------
__device__ float g_predcat[NI*H2];   // concat(pred_dec, pred_gls) [N,2H]
__device__ float g_score[NI];
__device__ int   g_sel;
__device__ int   g_flag;
__device__ float g_bias_attn[H];     // sel_mg@W1 + W1_b + W2_b
__device__ float g_bias_v[H];        // sel_mg@V1 + V1_b + V2_b
__device__ float g_M[H*2];           // U_w @ cls_w
__device__ float g_c2[2];            // U_b @ cls_w
__device__ float g_logit_part[(size_t)RR*12];
__device__ float g_rv_part[(size_t)RR*24];  // [r][12][2]

// fp16 operands
__device__ __half g_Ah[(size_t)RR*H2];       // big-GEMM A (~100.7 MB); [r][0:768]=dec row, [768:1536]=gls row
__device__ __half g_Bh[(size_t)H2*H2];       // big-GEMM B [n][k]; n<768: W2 col n, else V2 col n-768
__device__ __half g_Fh[(size_t)NI*H2];       // feat hi  [n][k]
__device__ __half g_Fl[(size_t)NI*H2];       // feat lo
__device__ __half g_S1h[(size_t)H*H2];       // s1_w^T hi [o][i]
__device__ __half g_S1l[(size_t)H*H2];       // s1_w^T lo

// ---------------- helpers ----------------
__device__ __forceinline__ float wsum(float v){
    #pragma unroll
    for (int o=16;o;o>>=1) v += __shfl_xor_sync(0xffffffffu, v, o);
    return v;
}
__device__ __forceinline__ uint32_t smem_u32(const void* p){
    uint32_t a;
    asm("{ .reg .u64 t; cvta.to.shared.u64 t, %1; cvt.u32.u64 %0, t; }" : "=r"(a) : "l"(p));
    return a;
}
__device__ __forceinline__ void ldm4(uint32_t* r, uint32_t addr){
    asm volatile("ldmatrix.sync.aligned.m8n8.x4.shared.b16 {%0,%1,%2,%3}, [%4];"
        : "=r"(r[0]),"=r"(r[1]),"=r"(r[2]),"=r"(r[3]) : "r"(addr));
}
__device__ __forceinline__ void mma_f16(float* c, const uint32_t* a, uint32_t b0, uint32_t b1){
    asm volatile("mma.sync.aligned.m16n8k16.row.col.f32.f16.f16.f32 "
        "{%0,%1,%2,%3}, {%4,%5,%6,%7}, {%8,%9}, {%0,%1,%2,%3};"
        : "+f"(c[0]),"+f"(c[1]),"+f"(c[2]),"+f"(c[3])
        : "r"(a[0]),"r"(a[1]),"r"(a[2]),"r"(a[3]), "r"(b0),"r"(b1));
}
__device__ __forceinline__ void cpa16(uint32_t s, const void* g){
    asm volatile("cp.async.cg.shared.global [%0], [%1], 16;" :: "r"(s), "l"(g));
}
__device__ __forceinline__ void cpa_commit(){ asm volatile("cp.async.commit_group;" ::: "memory"); }
__device__ __forceinline__ void cpa_wait1(){ asm volatile("cp.async.wait_group 1;" ::: "memory"); }

// ---------------- L1: pool(+conversions) / W2|V2 transpose / s1_w transpose+split ----------------
__global__ void k_pool_conv(const float* __restrict__ dec, const float* __restrict__ gls,
                            const int* __restrict__ pred,
                            const float* __restrict__ W2, const float* __restrict__ V2,
                            const float* __restrict__ s1w){
    int bid = blockIdx.x;
    if (bid == 0 && threadIdx.x == 0) g_flag = 0;
    if (bid < NI){
        int n = bid;
        int p = pred[n];
        if (threadIdx.x == 0) g_score[n] = 0.f;
        const float* db = dec + (size_t)n*KSEN*H;
        const float* gb = gls + (size_t)n*KSEN*H;
        for (int dp = threadIdx.x; dp < H/2; dp += blockDim.x){
            int d = dp*2;
            float sd0=0.f, sd1=0.f, sg0=0.f, sg1=0.f;
            #pragma unroll
            for (int k=0;k<KSEN;k++){
                float2 vd = *(const float2*)(db + k*H + d);
                float2 vg = *(const float2*)(gb + k*H + d);
                sd0 += vd.x; sd1 += vd.y; sg0 += vg.x; sg1 += vg.y;
                size_t r = (size_t)(n*KSEN + k);
                *(__half2*)(g_Ah + r*H2 + d)     = __floats2half2_rn(vd.x, vd.y);
                *(__half2*)(g_Ah + r*H2 + H + d) = __floats2half2_rn(vg.x, vg.y);
            }
            float2 pd = *(const float2*)(db + p*H + d);
            float2 pg = *(const float2*)(gb + p*H + d);
            float f0 = pd.x - sd0*(1.0f/16.0f), f1 = pd.y - sd1*(1.0f/16.0f);
            float h0 = pg.x - sg0*(1.0f/16.0f), h1 = pg.y - sg1*(1.0f/16.0f);
            __half fh0 = __float2half_rn(f0), fh1 = __float2half_rn(f1);
            __half hh0 = __float2half_rn(h0), hh1 = __float2half_rn(h1);
            size_t fb = (size_t)n*H2;
            *(__half2*)(g_Fh + fb + d)     = __half2(fh0, fh1);
            *(__half2*)(g_Fh + fb + H + d) = __half2(hh0, hh1);
            *(__half2*)(g_Fl + fb + d)     = __floats2half2_rn(f0-__half2float(fh0), f1-__half2float(fh1));
            *(__half2*)(g_Fl + fb + H + d) = __floats2half2_rn(h0-__half2float(hh0), h1-__half2float(hh1));
            *(float2*)(g_predcat + fb + d)     = pd;
            *(float2*)(g_predcat + fb + H + d) = pg;
        }
    } else if (bid < NI + 2304){
        __shared__ float tile[32][33];
        int cbid = bid - NI;
        int nb = cbid / 48;
        int kb = cbid % 48;
        int tx = threadIdx.x & 31, ty = threadIdx.x >> 5;
        const float* src = (nb < 24) ? W2 : V2;
        int col0 = (nb % 24) * 32;
        #pragma unroll
        for (int j=0;j<4;j++){
            int kk = ty + j*8;
            tile[tx][kk] = src[(size_t)(kb*32 + kk)*H + col0 + tx];
        }
        __syncthreads();
        int n0 = nb*32;
        #pragma unroll
        for (int j=0;j<4;j++){
            int c = ty + j*8;
            size_t di = (size_t)(n0 + c)*H2 + kb*32 + tx;
            g_Bh[di] = __float2half_rn(tile[c][tx]);
        }
    } else {
        __shared__ float tile[32][33];
        int cbid = bid - NI - 2304;
        int ob = cbid / 48;
        int kb = cbid % 48;
        int tx = threadIdx.x & 31, ty = threadIdx.x >> 5;
        int o0 = ob*32;
        #pragma unroll
        for (int j=0;j<4;j++){
            int kk = ty + j*8;
            tile[tx][kk] = s1w[(size_t)(kb*32 + kk)*H + o0 + tx];
        }
        __syncthreads();
        #pragma unroll
        for (int j=0;j<4;j++){
            int c = ty + j*8;
            float v = tile[c][tx];
            __half hi = __float2half_rn(v);
            size_t di = (size_t)(o0 + c)*H2 + kb*32 + tx;
            g_S1h[di] = hi;
            g_S1l[di] = __float2half_rn(v - __half2float(hi));
        }
    }
}

// ---------------- L2: tensor-core gemm1: score partials via 3-product fp16 split ----------------
#define G1_REGION 18432
#define G1_STAGE  73728
#define G1_SMEM   (3*G1_STAGE)
#define G1_ITERS  24

__device__ __forceinline__ void g1_load_stage(uint32_t sb, int stage, int by, int cb, int gk, int tid){
    uint32_t s0 = sb + stage*G1_STAGE;
    #pragma unroll
    for (int j=0;j<16;j++){
        int idx = j*256 + tid;
        int region = idx >> 10;
        int cl = idx & 1023;
        int r  = cl >> 3;
        int kc = cl & 7;
        const __half* g;
        size_t grow;
        if (region == 0){ g = g_Fh;  grow = (size_t)(by*128 + r); }
        else if (region == 1){ g = g_Fl;  grow = (size_t)(by*128 + r); }
        else if (region == 2){ g = g_S1h; grow = (size_t)(cb*128 + r); }
        else { g = g_S1l; grow = (size_t)(cb*128 + r); }
        cpa16(s0 + region*G1_REGION + r*144 + kc*16, g + grow*H2 + gk + kc*8);
    }
}

__global__ void __launch_bounds__(256,1) k_gemm1t(const float* __restrict__ s1b,
                                                  const float* __restrict__ s2w){
    extern __shared__ char smem[];
    uint32_t sb = smem_u32(smem);
    int tid = threadIdx.x;
    int cb = blockIdx.x, by = blockIdx.y;
    int warp = tid >> 5, lane = tid & 31;
    int wm = warp & 3, wn = warp >> 2;

    float acc[2][8][4];
    #pragma unroll
    for (int mt=0;mt<2;mt++)
        #pragma unroll
        for (int nt=0;nt<8;nt++)
            #pragma unroll
            for (int d=0;d<4;d++) acc[mt][nt][d] = 0.f;

    g1_load_stage(sb, 0, by, cb, 0,  tid); cpa_commit();
    g1_load_stage(sb, 1, by, cb, 64, tid); cpa_commit();

    int m8 = lane >> 3, r8 = lane & 7;

    for (int it = 0; it < G1_ITERS; it++){
        cpa_wait1();
        __syncthreads();
        if (it + 2 < G1_ITERS) g1_load_stage(sb, (it+2)%3, by, cb, (it+2)*64, tid);
        cpa_commit();

        uint32_t st = sb + (it%3)*G1_STAGE;
        #pragma unroll
        for (int kh=0; kh<4; kh++){
            int k0 = kh*16;
            uint32_t ah[2][4], al[2][4], bb[4][4];
            #pragma unroll
            for (int mt=0;mt<2;mt++){
                int rowA = wm*32 + mt*16 + (m8&1)*8 + r8;
                int kA   = k0 + (m8>>1)*8;
                uint32_t aoff = rowA*144 + kA*2;
                ldm4(ah[mt], st + 0*G1_REGION + aoff);
                ldm4(al[mt], st + 1*G1_REGION + aoff);
            }
            int rowB = wn*64 + (m8>>1)*8 + r8;
            int kB   = k0 + (m8&1)*8;
            uint32_t boff = rowB*144 + kB*2;
            #pragma unroll
            for (int ntp=0;ntp<4;ntp++) ldm4(bb[ntp], st + 2*G1_REGION + boff + ntp*16*144);
            #pragma unroll
            for (int mt=0;mt<2;mt++)
                #pragma unroll
                for (int nt=0;nt<8;nt++)
                    mma_f16(acc[mt][nt], ah[mt], bb[nt>>1][(nt&1)*2], bb[nt>>1][(nt&1)*2+1]);
            #pragma unroll
            for (int mt=0;mt<2;mt++)
                #pragma unroll
                for (int nt=0;nt<8;nt++)
                    mma_f16(acc[mt][nt], al[mt], bb[nt>>1][(nt&1)*2], bb[nt>>1][(nt&1)*2+1]);
            #pragma unroll
            for (int ntp=0;ntp<4;ntp++) ldm4(bb[ntp], st + 3*G1_REGION + boff + ntp*16*144);
            #pragma unroll
            for (int mt=0;mt<2;mt++)
                #pragma unroll
                for (int nt=0;nt<8;nt++)
                    mma_f16(acc[mt][nt], ah[mt], bb[nt>>1][(nt&1)*2], bb[nt>>1][(nt&1)*2+1]);
        }
    }

    int quad = lane >> 2, qt = lane & 3;
    int colb = cb*128;
    #pragma unroll
    for (int mt=0;mt<2;mt++){
        float plo = 0.f, phi = 0.f;
        #pragma unroll
        for (int nt=0;nt<8;nt++){
            int g0 = colb + wn*64 + nt*8 + qt*2;
            float b0 = s1b[g0], b1 = s1b[g0+1];
            float w0 = s2w[g0], w1 = s2w[g0+1];
            float x;
            x = acc[mt][nt][0]+b0; x = x>0.f? x:0.f; plo += x*w0;
            x = acc[mt][nt][1]+b1; x = x>0.f? x:0.f; plo += x*w1;
            x = acc[mt][nt][2]+b0; x = x>0.f? x:0.f; phi += x*w0;
            x = acc[mt][nt][3]+b1; x = x>0.f? x:0.f; phi += x*w1;
        }
        plo += __shfl_xor_sync(0xffffffffu, plo, 1);
        plo += __shfl_xor_sync(0xffffffffu, plo, 2);
        phi += __shfl_xor_sync(0xffffffffu, phi, 1);
        phi += __shfl_xor_sync(0xffffffffu, phi, 2);
        if (qt == 0){
            int rlo = by*128 + wm*32 + mt*16 + quad;
            atomicAdd(&g_score[rlo],   plo);
            atomicAdd(&g_score[rlo+8], phi);
        }
    }
}

// ---------------- L3: softmax (block 0) + sel-dependent biases + M (blocks 1..36) ----------------
__global__ void __launch_bounds__(1024) k_softmax_bias(
    float* __restrict__ probs,
    const float* __restrict__ W1, const float* __restrict__ W1b, const float* __restrict__ W2b,
    const float* __restrict__ V1, const float* __restrict__ V1b, const float* __restrict__ V2b,
    const float* __restrict__ Uw, const float* __restrict__ Ub,
    const float* __restrict__ clsw){
    int b = blockIdx.x, tid = threadIdx.x;
    if (b == 0){
        __shared__ float sv[1024];
        __shared__ int   si[1024];
        float a=g_score[tid], bb=g_score[tid+1024];
        float m; int mi;
        if (a>=bb){ m=a; mi=tid; } else { m=bb; mi=tid+1024; }
        sv[tid]=m; si[tid]=mi;
        __syncthreads();
        for (int s=512;s>0;s>>=1){
            if (tid<s){
                float ov=sv[tid+s]; int oi=si[tid+s];
                if (ov>sv[tid] || (ov==sv[tid] && oi<si[tid])){ sv[tid]=ov; si[tid]=oi; }
            }
            __syncthreads();
        }
        float mx = sv[0]; int sel = si[0];
        if (tid==0) g_sel = sel;
        __syncthreads();
        float e0 = expf(a-mx), e1 = expf(bb-mx);
        sv[tid] = e0+e1;
        __syncthreads();
        for (int s=512;s>0;s>>=1){ if (tid<s) sv[tid]+=sv[tid+s]; __syncthreads(); }
        float inv = 1.0f/sv[0];
        probs[tid]      = e0*inv;
        probs[tid+1024] = e1*inv;
        __threadfence();
        __syncthreads();
        if (tid==0) atomicExch(&g_flag, 1);
        return;
    }
    if (tid == 0){ while (atomicAdd(&g_flag, 0) == 0) __nanosleep(64); }
    __syncthreads();
    __threadfence();
    if (b <= 12){
        __shared__ float red[8][128];
        int g = b - 1;
        int half = (g >= 6);
        int jbase = (half ? g-6 : g) * 128;
        int jj = tid & 127, c = tid >> 7;
        int sel = g_sel;
        const float* m = half ? V1 : W1;
        const float* srow = g_predcat + (size_t)sel*H2;
        int j = jbase + jj;
        float s = 0.f;
        int i0 = c*192;
        #pragma unroll 4
        for (int i=i0; i<i0+192; i++) s += srow[i]*m[(size_t)i*H + j];
        red[c][jj] = s;
        __syncthreads();
        if (c == 0){
            float t = 0.f;
            #pragma unroll
            for (int cc=0; cc<8; cc++) t += red[cc][jj];
            if (half) g_bias_v[j]    = t + V1b[j] + V2b[j];
            else      g_bias_attn[j] = t + W1b[j] + W2b[j];
        }
    } else {
        int w = tid >> 5, lane = tid & 31;
        int j = (b-13)*32 + w;
        const float* ur = Uw + (size_t)j*H;
        float m0=0.f, m1=0.f;
        for (int t=lane; t<H; t+=32){ float u=ur[t]; m0+=u*clsw[2*t]; m1+=u*clsw[2*t+1]; }
        m0 = wsum(m0); m1 = wsum(m1);
        if (lane==0){ g_M[2*j]=m0; g_M[2*j+1]=m1; }
        if (b==13 && w==1){
            float s0=0.f, s1=0.f;
            for (int t=lane; t<H; t+=32){ float u=Ub[t]; s0+=u*clsw[2*t]; s1+=u*clsw[2*t+1]; }
            s0 = wsum(s0); s1 = wsum(s1);
            if (lane==0){ g_c2[0]=s0; g_c2[1]=s1; }
        }
    }
}

// ---------------- L4: mma.sync fp16 GEMM (256 thr, 32x64 warp tiles) + reduce ----------------
// grid (12, 256), CTA 128x128, 256 thr, warps 4(M)x2(N), 3-stage K64 pipeline, occ 2.
// Next-stage cp.async issues interleaved across the 4 kh chunks (no front-batch).
#define KB_REGION 18432
#define KB_STAGE  36864
#define KB_SMEM   (3*KB_STAGE)
#define KB_ITERS  24

__device__ __forceinline__ void kb_load_chunk(uint32_t sb, int stage, int by, int cb, int gk,
                                              int tid, int chunk){
    uint32_t s0 = sb + stage*KB_STAGE;
    #pragma unroll
    for (int jj=0;jj<2;jj++){
        int idx = (chunk*2+jj)*256 + tid;   // 0..2047
        int region = idx >> 10;             // 0 A, 1 Bh
        int cl = idx & 1023;
        int r  = cl >> 3;
        int kc = cl & 7;
        const __half* g = region ? g_Bh : g_Ah;
        size_t grow = region ? (size_t)(cb*128 + r) : (size_t)(by*128 + r);
        cpa16(s0 + region*KB_REGION + r*144 + kc*16, g + grow*H2 + gk + kc*8);
    }
}

__global__ void __launch_bounds__(256,2) k_big_mma(const float* __restrict__ Wa){
    extern __shared__ char smem[];
    uint32_t sb = smem_u32(smem);
    int tid = threadIdx.x;
    int cb = blockIdx.x, by = blockIdx.y;
    int warp = tid >> 5, lane = tid & 31;
    int wm = warp & 3, wn = warp >> 2;

    float acc[2][8][4];
    #pragma unroll
    for (int mt=0;mt<2;mt++)
        #pragma unroll
        for (int nt=0;nt<8;nt++)
            #pragma unroll
            for (int d=0;d<4;d++) acc[mt][nt][d] = 0.f;

    #pragma unroll
    for (int c=0;c<4;c++) kb_load_chunk(sb, 0, by, cb, 0,  tid, c);
    cpa_commit();
    #pragma unroll
    for (int c=0;c<4;c++) kb_load_chunk(sb, 1, by, cb, 64, tid, c);
    cpa_commit();

    int m8 = lane >> 3, r8 = lane & 7;

    for (int it = 0; it < KB_ITERS; it++){
        cpa_wait1();
        __syncthreads();
        int do_load = (it + 2 < KB_ITERS);
        int ns = (it+2)%3, ngk = (it+2)*64;

        uint32_t st = sb + (it%3)*KB_STAGE;
        #pragma unroll
        for (int kh=0; kh<4; kh++){
            if (do_load) kb_load_chunk(sb, ns, by, cb, ngk, tid, kh);
            int k0 = kh*16;
            uint32_t ah[2][4], bb[4][4];
            #pragma unroll
            for (int mt=0;mt<2;mt++){
                int rowA = wm*32 + mt*16 + (m8&1)*8 + r8;
                int kA   = k0 + (m8>>1)*8;
                ldm4(ah[mt], st + 0*KB_REGION + rowA*144 + kA*2);
            }
            int rowB = wn*64 + (m8>>1)*8 + r8;
            int kB   = k0 + (m8&1)*8;
            uint32_t boff = rowB*144 + kB*2;
            #pragma unroll
            for (int ntp=0;ntp<4;ntp++) ldm4(bb[ntp], st + 1*KB_REGION + boff + ntp*16*144);
            #pragma unroll
            for (int mt=0;mt<2;mt++)
                #pragma unroll
                for (int nt=0;nt<8;nt++)
                    mma_f16(acc[mt][nt], ah[mt], bb[nt>>1][(nt&1)*2], bb[nt>>1][(nt&1)*2+1]);
        }
        cpa_commit();
    }

    // ---------------- epilogue: reduce over the 128 columns this CTA owns ----------------
    int quad = lane >> 2, qt = lane & 3;
    if (cb < 6){
        int colb = cb*128;
        #pragma unroll
        for (int mt=0;mt<2;mt++){
            float plo = 0.f, phi = 0.f;
            #pragma unroll
            for (int nt=0;nt<8;nt++){
                int g0 = colb + wn*64 + nt*8 + qt*2;
                float ba0 = g_bias_attn[g0],  ba1 = g_bias_attn[g0+1];
                float w0  = Wa[g0],           w1  = Wa[g0+1];
                plo += tanhf(acc[mt][nt][0]+ba0)*w0 + tanhf(acc[mt][nt][1]+ba1)*w1;
                phi += tanhf(acc[mt][nt][2]+ba0)*w0 + tanhf(acc[mt][nt][3]+ba1)*w1;
            }
            plo += __shfl_xor_sync(0xffffffffu, plo, 1);
            plo += __shfl_xor_sync(0xffffffffu, plo, 2);
            phi += __shfl_xor_sync(0xffffffffu, phi, 1);
            phi += __shfl_xor_sync(0xffffffffu, phi, 2);
            if (qt == 0){
                int rlo = by*128 + wm*32 + mt*16 + quad;
                g_logit_part[(size_t)rlo*12 + cb*2 + wn]     = plo;
                g_logit_part[(size_t)(rlo+8)*12 + cb*2 + wn] = phi;
            }
        }
    } else {
        int cbv = cb - 6, colb = cbv*128, slot = cbv*2 + wn;
        #pragma unroll
        for (int mt=0;mt<2;mt++){
            float p0l=0.f, p1l=0.f, p0h=0.f, p1h=0.f;
            #pragma unroll
            for (int nt=0;nt<8;nt++){
                int g0 = colb + wn*64 + nt*8 + qt*2;
                float bv0 = g_bias_v[g0], bv1 = g_bias_v[g0+1];
                float m00 = g_M[2*g0],   m01 = g_M[2*g0+1];
                float m10 = g_M[2*g0+2], m11 = g_M[2*g0+3];
                float x;
                x = acc[mt][nt][0]+bv0; x = x>0.f? x:0.f; p0l += x*m00; p1l += x*m01;
                x = acc[mt][nt][1]+bv1; x = x>0.f? x:0.f; p0l += x*m10; p1l += x*m11;
                x = acc[mt][nt][2]+bv0; x = x>0.f? x:0.f; p0h += x*m00; p1h += x*m01;
                x = acc[mt][nt][3]+bv1; x = x>0.f? x:0.f; p0h += x*m10; p1h += x*m11;
            }
            p0l += __shfl_xor_sync(0xffffffffu, p0l, 1); p0l += __shfl_xor_sync(0xffffffffu, p0l, 2);
            p1l += __shfl_xor_sync(0xffffffffu, p1l, 1); p1l += __shfl_xor_sync(0xffffffffu, p1l, 2);
            p0h += __shfl_xor_sync(0xffffffffu, p0h, 1); p0h += __shfl_xor_sync(0xffffffffu, p0h, 2);
            p1h += __shfl_xor_sync(0xffffffffu, p1h, 1); p1h += __shfl_xor_sync(0xffffffffu, p1h, 2);
            if (qt == 0){
                int rlo = by*128 + wm*32 + mt*16 + quad;
                g_rv_part[(size_t)rlo*24 + slot*2 + 0] = p0l;
                g_rv_part[(size_t)rlo*24 + slot*2 + 1] = p1l;
                g_rv_part[(size_t)(rlo+8)*24 + slot*2 + 0] = p0h;
                g_rv_part[(size_t)(rlo+8)*24 + slot*2 + 1] = p1h;
            }
        }
    }
}

// ---------------- L5: fused per-instance attn softmax + final logits ----------------
// dec read in fp16 from g_Ah (first H columns of each A row = dec row).
__global__ void __launch_bounds__(512) k_attn_final(const float* __restrict__ clsw,
                                                    const float* __restrict__ clsb,
                                                    float* __restrict__ out){
    __shared__ float slg[16];
    __shared__ float sat[16];
    int n = blockIdx.x;
    int w = threadIdx.x >> 5, lane = threadIdx.x & 31;
    int r = n*KSEN + w;
    const __half* drow = g_Ah + (size_t)r*H2;
    float a0=0.f, a1=0.f;
    #pragma unroll 4
    for (int t=lane*2; t<H; t+=64){
        __half2 d2 = *(const __half2*)(drow + t);
        float4 cw = *(const float4*)(clsw + 2*t);
        float dx = __half2float(d2.x), dy = __half2float(d2.y);
        a0 += dx*cw.x + dy*cw.z;
        a1 += dx*cw.y + dy*cw.w;
    }
    a0 = wsum(a0); a1 = wsum(a1);
    float lgp = (lane < 12) ? g_logit_part[(size_t)r*12 + lane] : 0.f;
    float lg = wsum(lgp);
    if (lane == 0) slg[w] = lg;
    __syncthreads();
    if (w == 0){
        float v = (lane < 16) ? slg[lane] : -INFINITY;
        float m = v;
        #pragma unroll
        for (int o=16;o;o>>=1) m = fmaxf(m, __shfl_xor_sync(0xffffffffu, m, o));
        float e = (lane < 16) ? expf(v - m) : 0.f;
        float s = wsum(e);
        if (lane < 16) sat[lane] = e/s;
    }
    float rv0p = (lane < 12) ? g_rv_part[(size_t)r*24 + lane*2]     : 0.f;
    float rv1p = (lane < 12) ? g_rv_part[(size_t)r*24 + lane*2 + 1] : 0.f;
    float rv0 = wsum(rv0p), rv1 = wsum(rv1p);
    __syncthreads();
    if (lane == 0){
        float o0 = a0 + clsb[0], o1 = a1 + clsb[1];
        if (n != g_sel){
            float at = sat[w];
            o0 += at*(rv0 + g_c2[0]);
            o1 += at*(rv1 + g_c2[1]);
        }
        out[2*r]   = o0;
        out[2*r+1] = o1;
    }
}

// ---------------- launcher ----------------
extern "C" void kernel_launch(void* const* d_in, const int* in_sizes, int n_in,
                              void* d_out, int out_size){
    (void)n_in; (void)out_size;
    const float *dec,*gls,*s1w,*s1b,*s2w,*s2b,*W1w,*W1b,*W2w,*W2b,*Waw,*Wab,*V1w,*V1b,*V2w,*V2b,*Uw,*Ub,*clsw,*clsb;
    const int* pred;
    if (in_sizes[2] == NI){
        dec=(const float*)d_in[0]; gls=(const float*)d_in[1]; pred=(const int*)d_in[2];
        s1w=(const float*)d_in[3];  s1b=(const float*)d_in[4];
        s2w=(const float*)d_in[5];  s2b=(const float*)d_in[6];
        W1w=(const float*)d_in[7];  W1b=(const float*)d_in[8];
        W2w=(const float*)d_in[9];  W2b=(const float*)d_in[10];
        Waw=(const float*)d_in[11]; Wab=(const float*)d_in[12];
        V1w=(const float*)d_in[13]; V1b=(const float*)d_in[14];
        V2w=(const float*)d_in[15]; V2b=(const float*)d_in[16];
        Uw =(const float*)d_in[17]; Ub =(const float*)d_in[18];
        clsw=(const float*)d_in[19]; clsb=(const float*)d_in[20];
    } else {
        dec=(const float*)d_in[0]; gls=(const float*)d_in[1];
        s1w=(const float*)d_in[2];  s1b=(const float*)d_in[3];
        s2w=(const float*)d_in[4];  s2b=(const float*)d_in[5];
        W1w=(const float*)d_in[6];  W1b=(const float*)d_in[7];
        W2w=(const float*)d_in[8];  W2b=(const float*)d_in[9];
        Waw=(const float*)d_in[10]; Wab=(const float*)d_in[11];
        V1w=(const float*)d_in[12]; V1b=(const float*)d_in[13];
        V2w=(const float*)d_in[14]; V2b=(const float*)d_in[15];
        Uw =(const float*)d_in[16]; Ub =(const float*)d_in[17];
        clsw=(const float*)d_in[18]; clsb=(const float*)d_in[19];
        pred=(const int*)d_in[20];
    }
    (void)s2b; (void)Wab;
    float* out = (float*)d_out;

    cudaFuncSetAttribute(k_gemm1t,  cudaFuncAttributeMaxDynamicSharedMemorySize, G1_SMEM);
    cudaFuncSetAttribute(k_big_mma, cudaFuncAttributeMaxDynamicSharedMemorySize, KB_SMEM);

    k_pool_conv   <<<NI + 2304 + 1152, 256>>>(dec, gls, pred, W2w, V2w, s1w);
    k_gemm1t      <<<dim3(6,16), 256, G1_SMEM>>>(s1b, s2w);
    k_softmax_bias<<<37, 1024>>>(out + 2*RR, W1w, W1b, W2b, V1w, V1b, V2b, Uw, Ub, clsw);
    k_big_mma     <<<dim3(12, 256), 256, KB_SMEM>>>(Waw);   // launch #4 -> profiled
    k_attn_final  <<<NI, 512>>>(clsw, clsb, out);
}